// round 2
// baseline (speedup 1.0000x reference)
#include <cuda_runtime.h>
#include <cstdint>

#define N_SRC0 400000
#define N_DST0 200000
#define N_DST1 100000
#define E0 3200000
#define E1 1600000
#define INF 128
#define HF 256
#define NC 8

// ---------------- device scratch (allocation-free rule: __device__ globals) ----
__device__ float g_h[(size_t)N_SRC0 * INF];      // gated features     204.8 MB
__device__ float g_agg1[(size_t)N_DST0 * INF];   // layer1 sum agg     102.4 MB
__device__ float g_deg1[N_DST0];
__device__ float g_h1[(size_t)N_DST0 * HF];      // layer1 output      204.8 MB
__device__ float g_p1[N_DST0 * NC];              // h1 @ W_neigh2 (pre-projected msgs)
__device__ float g_self2[N_DST1 * NC];           // h1[:100k] @ W_self2
__device__ float g_agg2[N_DST1 * NC];
__device__ float g_deg2[N_DST1];

__device__ __forceinline__ void red_add_v4(float* p, float4 v) {
    asm volatile("red.global.add.v4.f32 [%0], {%1,%2,%3,%4};"
                 :: "l"(p), "f"(v.x), "f"(v.y), "f"(v.z), "f"(v.w) : "memory");
}

// ---------------- 0) zero accumulators -----------------------------------------
// regions (floats): agg1 25,600,000 | deg1 200,000 | agg2 800,000 | deg2 100,000
__global__ void zero_kernel() {
    long i = ((long)blockIdx.x * blockDim.x + threadIdx.x) * 4;
    float4 z = make_float4(0.f, 0.f, 0.f, 0.f);
    if (i < 25600000L) {
        *(float4*)&g_agg1[i] = z;
    } else if (i < 25800000L) {
        *(float4*)&g_deg1[i - 25600000L] = z;
    } else if (i < 26600000L) {
        *(float4*)&g_agg2[i - 25800000L] = z;
    } else if (i < 26700000L) {
        *(float4*)&g_deg2[i - 26600000L] = z;
    }
}

// ---------------- 1) gated features: h = feat * sigmoid(emb[cid]) --------------
// warp per node row; lane handles 4 feats
__global__ __launch_bounds__(256) void gate_kernel(const float* __restrict__ x,
                                                   const float* __restrict__ emb) {
    int gid = blockIdx.x * blockDim.x + threadIdx.x;
    int w = gid >> 5, lane = gid & 31;
    if (w >= N_SRC0) return;
    const float* xr = x + (size_t)w * (INF + 1);
    int cid = (int)xr[0];
    float4 e4 = *(const float4*)(emb + (size_t)cid * INF + lane * 4);
    float f0 = xr[1 + lane * 4 + 0];
    float f1 = xr[1 + lane * 4 + 1];
    float f2 = xr[1 + lane * 4 + 2];
    float f3 = xr[1 + lane * 4 + 3];
    float4 o;
    o.x = f0 * (1.f / (1.f + __expf(-e4.x)));
    o.y = f1 * (1.f / (1.f + __expf(-e4.y)));
    o.z = f2 * (1.f / (1.f + __expf(-e4.z)));
    o.w = f3 * (1.f / (1.f + __expf(-e4.w)));
    *(float4*)&g_h[(size_t)w * INF + lane * 4] = o;
}

// ---------------- 2) layer-1 edge aggregation (warp per edge) ------------------
__global__ __launch_bounds__(256) void edge1_kernel(const int* __restrict__ src,
                                                    const int* __restrict__ dst) {
    int gid = blockIdx.x * blockDim.x + threadIdx.x;
    int e = gid >> 5, lane = gid & 31;
    if (e >= E0) return;
    int s = src[e], d = dst[e];
    float4 v = *(const float4*)(g_h + (size_t)s * INF + lane * 4);
    red_add_v4(g_agg1 + (size_t)d * INF + lane * 4, v);
    if (lane == 0) atomicAdd(&g_deg1[d], 1.0f);
}

// ---------------- 3) normalize agg1 by degree in place -------------------------
__global__ __launch_bounds__(256) void norm1_kernel() {
    int gid = blockIdx.x * blockDim.x + threadIdx.x;
    int w = gid >> 5, lane = gid & 31;
    if (w >= N_DST0) return;
    float inv = 1.f / fmaxf(g_deg1[w], 1.f);
    float4* p = (float4*)(g_agg1 + (size_t)w * INF);
    float4 v = p[lane];
    v.x *= inv; v.y *= inv; v.z *= inv; v.w *= inv;
    p[lane] = v;
}

// ---------------- 4) layer-1 fused GEMM: h1 = relu([h|aggn] @ [Ws1;Wn1] + b1) --
// BM=128, BN=128, BK=8, 256 threads, 8x8 per thread
__global__ __launch_bounds__(256, 2) void gemm1_kernel(const float* __restrict__ Ws1,
                                                       const float* __restrict__ Wn1,
                                                       const float* __restrict__ b1) {
    __shared__ __align__(16) float As[8][132];  // transposed A tile (pad 4)
    __shared__ __align__(16) float Bs[8][128];
    int tid = threadIdx.x;
    int row0 = blockIdx.x * 128;
    int n0 = blockIdx.y * 128;
    int arow = tid >> 1;
    int acol4 = (tid & 1) * 4;
    int brow = tid >> 5;
    int bcol4 = (tid & 31) * 4;
    int ty = tid >> 4, tx = tid & 15;

    float acc[8][8];
#pragma unroll
    for (int i = 0; i < 8; i++)
#pragma unroll
        for (int j = 0; j < 8; j++) acc[i][j] = 0.f;

    for (int kt = 0; kt < 32; kt++) {
        int k0 = kt * 8;
        const float* Ab;
        const float* Wb;
        int kA;
        if (k0 < 128) { Ab = g_h;    Wb = Ws1; kA = k0; }
        else          { Ab = g_agg1; Wb = Wn1; kA = k0 - 128; }

        int gr = row0 + arow;
        float4 av = make_float4(0.f, 0.f, 0.f, 0.f);
        if (gr < N_DST0) av = *(const float4*)(Ab + (size_t)gr * INF + kA + acol4);
        float4 bv = *(const float4*)(Wb + (size_t)(kA + brow) * HF + n0 + bcol4);

        __syncthreads();
        As[acol4 + 0][arow] = av.x;
        As[acol4 + 1][arow] = av.y;
        As[acol4 + 2][arow] = av.z;
        As[acol4 + 3][arow] = av.w;
        *(float4*)&Bs[brow][bcol4] = bv;
        __syncthreads();

#pragma unroll
        for (int k = 0; k < 8; k++) {
            float a[8], b[8];
            *(float4*)&a[0] = *(float4*)&As[k][ty * 8];
            *(float4*)&a[4] = *(float4*)&As[k][ty * 8 + 4];
            *(float4*)&b[0] = *(float4*)&Bs[k][tx * 8];
            *(float4*)&b[4] = *(float4*)&Bs[k][tx * 8 + 4];
#pragma unroll
            for (int i = 0; i < 8; i++)
#pragma unroll
                for (int j = 0; j < 8; j++)
                    acc[i][j] = fmaf(a[i], b[j], acc[i][j]);
        }
    }

    float4 bias0 = *(const float4*)(b1 + n0 + tx * 8);
    float4 bias1 = *(const float4*)(b1 + n0 + tx * 8 + 4);
#pragma unroll
    for (int i = 0; i < 8; i++) {
        int gr = row0 + ty * 8 + i;
        if (gr < N_DST0) {
            float4 v0, v1;
            v0.x = fmaxf(acc[i][0] + bias0.x, 0.f);
            v0.y = fmaxf(acc[i][1] + bias0.y, 0.f);
            v0.z = fmaxf(acc[i][2] + bias0.z, 0.f);
            v0.w = fmaxf(acc[i][3] + bias0.w, 0.f);
            v1.x = fmaxf(acc[i][4] + bias1.x, 0.f);
            v1.y = fmaxf(acc[i][5] + bias1.y, 0.f);
            v1.z = fmaxf(acc[i][6] + bias1.z, 0.f);
            v1.w = fmaxf(acc[i][7] + bias1.w, 0.f);
            *(float4*)&g_h1[(size_t)gr * HF + n0 + tx * 8] = v0;
            *(float4*)&g_h1[(size_t)gr * HF + n0 + tx * 8 + 4] = v1;
        }
    }
}

// ---------------- 5) projections: p1 = h1@Wn2 ; self2 = h1[:100k]@Ws2 ----------
// 16 rows per block, thread = (row, cc); cc<8 -> neigh, cc>=8 -> self
__global__ __launch_bounds__(256) void proj_kernel(const float* __restrict__ Wn2,
                                                   const float* __restrict__ Ws2) {
    __shared__ __align__(16) float h1s[16 * 260];
    __shared__ __align__(16) float wT[16 * 260];
    int tid = threadIdx.x;
    for (int i = tid; i < 4096; i += 256) {
        int k = i >> 4, cc = i & 15;
        wT[cc * 260 + k] = (cc < 8) ? Wn2[k * 8 + cc] : Ws2[k * 8 + (cc - 8)];
    }
    int r0 = blockIdx.x * 16;
    for (int j = tid; j < 1024; j += 256) {
        int i = j >> 6, k4 = j & 63;
        *(float4*)&h1s[i * 260 + k4 * 4] =
            *(const float4*)&g_h1[(size_t)(r0 + i) * HF + k4 * 4];
    }
    __syncthreads();

    int row = tid >> 4, cc = tid & 15;
    const float* hp = &h1s[row * 260];
    const float* wp = &wT[cc * 260];
    float acc = 0.f;
#pragma unroll 16
    for (int k = 0; k < 256; k += 4) {
        float4 h4 = *(const float4*)(hp + k);
        float4 w4 = *(const float4*)(wp + k);
        acc += h4.x * w4.x + h4.y * w4.y + h4.z * w4.z + h4.w * w4.w;
    }
    int m = r0 + row;
    if (cc < 8)            g_p1[m * NC + cc] = acc;
    else if (m < N_DST1)   g_self2[m * NC + (cc - 8)] = acc;
}

// ---------------- 6) layer-2 edge aggregation (thread per edge, 8-dim msgs) ----
__global__ __launch_bounds__(256) void edge2_kernel(const int* __restrict__ src,
                                                    const int* __restrict__ dst) {
    int e = blockIdx.x * blockDim.x + threadIdx.x;
    if (e >= E1) return;
    int s = src[e], d = dst[e];
    float4 v0 = *(const float4*)(g_p1 + (size_t)s * NC);
    float4 v1 = *(const float4*)(g_p1 + (size_t)s * NC + 4);
    red_add_v4(g_agg2 + (size_t)d * NC, v0);
    red_add_v4(g_agg2 + (size_t)d * NC + 4, v1);
    atomicAdd(&g_deg2[d], 1.0f);
}

// ---------------- 7) final: out = self2 + agg2/deg + b2 ------------------------
__global__ __launch_bounds__(256) void final_kernel(const float* __restrict__ b2,
                                                    float* __restrict__ out) {
    int t = blockIdx.x * blockDim.x + threadIdx.x;
    if (t >= N_DST1 * 2) return;
    int m = t >> 1, q = t & 1;
    float inv = 1.f / fmaxf(g_deg2[m], 1.f);
    float4 a = *(float4*)&g_agg2[m * NC + q * 4];
    float4 s = *(float4*)&g_self2[m * NC + q * 4];
    float4 bb = *(const float4*)(b2 + q * 4);
    float4 o;
    o.x = s.x + a.x * inv + bb.x;
    o.y = s.y + a.y * inv + bb.y;
    o.z = s.z + a.z * inv + bb.z;
    o.w = s.w + a.w * inv + bb.w;
    *(float4*)&out[m * NC + q * 4] = o;
}

// ---------------- host --------------------------------------------------------
extern "C" void kernel_launch(void* const* d_in, const int* in_sizes, int n_in,
                              void* d_out, int out_size) {
    const float* x    = (const float*)d_in[0];
    const int*   src0 = (const int*)d_in[1];
    const int*   dst0 = (const int*)d_in[2];
    const int*   src1 = (const int*)d_in[3];
    const int*   dst1 = (const int*)d_in[4];

    // locate emb by its size (3072) — robust to whether scalar n_dst args appear
    int ie = 5;
    while (ie < n_in && in_sizes[ie] != 24 * INF) ie++;
    const float* emb = (const float*)d_in[ie];
    const float* Ws1 = (const float*)d_in[ie + 1];
    const float* Wn1 = (const float*)d_in[ie + 2];
    const float* b1  = (const float*)d_in[ie + 3];
    const float* Ws2 = (const float*)d_in[ie + 4];
    const float* Wn2 = (const float*)d_in[ie + 5];
    const float* b2  = (const float*)d_in[ie + 6];

    zero_kernel<<<26076, 256>>>();
    gate_kernel<<<(N_SRC0 * 32) / 256, 256>>>(x, emb);
    edge1_kernel<<<(E0 * 32 + 255) / 256, 256>>>(src0, dst0);
    norm1_kernel<<<(N_DST0 * 32) / 256, 256>>>();
    dim3 g1((N_DST0 + 127) / 128, HF / 128);
    gemm1_kernel<<<g1, 256>>>(Ws1, Wn1, b1);
    proj_kernel<<<N_DST0 / 16, 256>>>(Wn2, Ws2);
    edge2_kernel<<<(E1 + 255) / 256, 256>>>(src1, dst1);
    final_kernel<<<(N_DST1 * 2 + 255) / 256, 256>>>(b2, (float*)d_out);
}

// round 7
// speedup vs baseline: 1.2131x; 1.2131x over previous
#include <cuda_runtime.h>
#include <cuda_bf16.h>
#include <cstdint>

#define N_SRC0 400000
#define N_DST0 200000
#define N_DST1 100000
#define E0 3200000
#define E1 1600000
#define INF 128
#define HF 256
#define NC 8

#define M_ROWS_PAD 200064   // 1563 * 128

// ---------------- device scratch ------------------------------------------------
__device__ float g_h[(size_t)N_SRC0 * INF];      // gated features
__device__ float g_agg1[(size_t)N_DST0 * INF];   // layer1 sum agg
__device__ float g_deg1[N_DST0];
__device__ float g_h1[(size_t)N_DST0 * HF];      // layer1 output
__device__ float g_p1[N_DST0 * NC];
__device__ float g_self2[N_DST1 * NC];
__device__ float g_agg2[N_DST1 * NC];
__device__ float g_deg2[N_DST1];
// split-bf16 GEMM operands
__device__ __align__(16) __nv_bfloat16 g_Abig[(size_t)M_ROWS_PAD * 512]; // [m][0:256)=hi | [256:512)=lo
__device__ __align__(16) __nv_bfloat16 g_Bhi[HF * 256];                  // [n][k] (k contig) hi
__device__ __align__(16) __nv_bfloat16 g_Blo[HF * 256];                  // lo

__device__ __forceinline__ void red_add_v4(float* p, float4 v) {
    asm volatile("red.global.add.v4.f32 [%0], {%1,%2,%3,%4};"
                 :: "l"(p), "f"(v.x), "f"(v.y), "f"(v.z), "f"(v.w) : "memory");
}

// ---------------- mma.sync helpers (sm_80+ baseline features) -------------------
__device__ __forceinline__ void ldsm_x4(uint32_t& r0, uint32_t& r1, uint32_t& r2,
                                        uint32_t& r3, uint32_t addr) {
    asm volatile("ldmatrix.sync.aligned.m8n8.x4.shared.b16 {%0,%1,%2,%3}, [%4];"
                 : "=r"(r0), "=r"(r1), "=r"(r2), "=r"(r3) : "r"(addr));
}
__device__ __forceinline__ void mma_16816(float* d, uint32_t a0, uint32_t a1,
                                          uint32_t a2, uint32_t a3,
                                          uint32_t b0, uint32_t b1) {
    asm volatile(
        "mma.sync.aligned.m16n8k16.row.col.f32.bf16.bf16.f32 "
        "{%0,%1,%2,%3}, {%4,%5,%6,%7}, {%8,%9}, {%0,%1,%2,%3};"
        : "+f"(d[0]), "+f"(d[1]), "+f"(d[2]), "+f"(d[3])
        : "r"(a0), "r"(a1), "r"(a2), "r"(a3), "r"(b0), "r"(b1));
}

// ---------------- 0) zero accumulators -----------------------------------------
__global__ void zero_kernel() {
    long i = ((long)blockIdx.x * blockDim.x + threadIdx.x) * 4;
    float4 z = make_float4(0.f, 0.f, 0.f, 0.f);
    if (i < 25600000L) {
        *(float4*)&g_agg1[i] = z;
    } else if (i < 25800000L) {
        *(float4*)&g_deg1[i - 25600000L] = z;
    } else if (i < 26600000L) {
        *(float4*)&g_agg2[i - 25800000L] = z;
    } else if (i < 26700000L) {
        *(float4*)&g_deg2[i - 26600000L] = z;
    }
}

// ---------------- 1) gate -------------------------------------------------------
__global__ __launch_bounds__(256) void gate_kernel(const float* __restrict__ x,
                                                   const float* __restrict__ emb) {
    int gid = blockIdx.x * blockDim.x + threadIdx.x;
    int w = gid >> 5, lane = gid & 31;
    if (w >= N_SRC0) return;
    const float* xr = x + (size_t)w * (INF + 1);
    int cid = (int)xr[0];
    float4 e4 = *(const float4*)(emb + (size_t)cid * INF + lane * 4);
    float f0 = xr[1 + lane * 4 + 0];
    float f1 = xr[1 + lane * 4 + 1];
    float f2 = xr[1 + lane * 4 + 2];
    float f3 = xr[1 + lane * 4 + 3];
    float4 o;
    o.x = f0 * (1.f / (1.f + __expf(-e4.x)));
    o.y = f1 * (1.f / (1.f + __expf(-e4.y)));
    o.z = f2 * (1.f / (1.f + __expf(-e4.z)));
    o.w = f3 * (1.f / (1.f + __expf(-e4.w)));
    *(float4*)&g_h[(size_t)w * INF + lane * 4] = o;
}

// ---------------- 2) layer-1 edge aggregation (warp per edge) -------------------
__global__ __launch_bounds__(256) void edge1_kernel(const int* __restrict__ src,
                                                    const int* __restrict__ dst) {
    int gid = blockIdx.x * blockDim.x + threadIdx.x;
    int e = gid >> 5, lane = gid & 31;
    if (e >= E0) return;
    int s = src[e], d = dst[e];
    float4 v = *(const float4*)(g_h + (size_t)s * INF + lane * 4);
    red_add_v4(g_agg1 + (size_t)d * INF + lane * 4, v);
    if (lane == 0) atomicAdd(&g_deg1[d], 1.0f);
}

// ---------------- 3) build split-bf16 A (fuses degree normalization) ------------
__global__ __launch_bounds__(256) void convertA_kernel() {
    int m = blockIdx.x;
    int k = threadIdx.x;
    float v = 0.f;
    if (m < N_DST0) {
        if (k < INF) {
            v = g_h[(size_t)m * INF + k];
        } else {
            float inv = 1.f / fmaxf(g_deg1[m], 1.f);
            v = g_agg1[(size_t)m * INF + (k - INF)] * inv;
        }
    }
    __nv_bfloat16 hi = __float2bfloat16(v);
    float lo = v - __bfloat162float(hi);
    g_Abig[(size_t)m * 512 + k] = hi;
    g_Abig[(size_t)m * 512 + 256 + k] = __float2bfloat16(lo);
}

// ---------------- 4) build split-bf16 B (transposed stacked weights) ------------
__global__ __launch_bounds__(256) void convertB_kernel(const float* __restrict__ Ws1,
                                                       const float* __restrict__ Wn1) {
    int k = blockIdx.x, n = threadIdx.x;
    float w = (k < INF) ? Ws1[(size_t)k * HF + n] : Wn1[(size_t)(k - INF) * HF + n];
    __nv_bfloat16 hi = __float2bfloat16(w);
    g_Bhi[n * 256 + k] = hi;
    g_Blo[n * 256 + k] = __float2bfloat16(w - __bfloat162float(hi));
}

// ---------------- 5) mma.sync GEMM: h1 = relu(A' @ B'^T + b1) -------------------
// split-bf16 3-term, effective K = 768 = 24 chunks of 32.
// CTA 128x128, 8 warps (4 M x 2 N), warp tile 32x64, reg-staged double buffer.
// smem rows padded to 40 bf16 (80B): conflict-free ldmatrix (20r mod 32 cycles all banks)
__device__ __forceinline__ void chunk_src(int c, int& ab,
                                          const __nv_bfloat16*& Bsrc, int& bb) {
    if (c < 8)       { ab = c * 32;            Bsrc = g_Bhi; bb = c * 32; }
    else if (c < 16) { ab = 256 + (c - 8) * 32; Bsrc = g_Bhi; bb = (c - 8) * 32; }
    else             { ab = (c - 16) * 32;      Bsrc = g_Blo; bb = (c - 16) * 32; }
}

__global__ __launch_bounds__(256, 2) void gemm1_mma_kernel(const float* __restrict__ b1) {
    __shared__ __align__(16) __nv_bfloat16 As[2][128 * 40];
    __shared__ __align__(16) __nv_bfloat16 Bs[2][128 * 40];
    int tid = threadIdx.x, lane = tid & 31, wid = tid >> 5;
    int warp_m = wid & 3, warp_n = wid >> 2;
    int row0 = blockIdx.x * 128, n0 = blockIdx.y * 128;

    float acc[2][8][4];
#pragma unroll
    for (int mt = 0; mt < 2; mt++)
#pragma unroll
        for (int nt = 0; nt < 8; nt++)
#pragma unroll
            for (int q = 0; q < 4; q++) acc[mt][nt][q] = 0.f;

    int u0 = tid, r0t = u0 >> 2, j0 = u0 & 3;
    int u1 = tid + 256, r1t = u1 >> 2, j1 = u1 & 3;

    // prologue: chunk 0 into buffer 0
    {
        int ab, bb; const __nv_bfloat16* Bsrc;
        chunk_src(0, ab, Bsrc, bb);
        *(uint4*)&As[0][r0t * 40 + j0 * 8] =
            *(const uint4*)&g_Abig[(size_t)(row0 + r0t) * 512 + ab + j0 * 8];
        *(uint4*)&As[0][r1t * 40 + j1 * 8] =
            *(const uint4*)&g_Abig[(size_t)(row0 + r1t) * 512 + ab + j1 * 8];
        *(uint4*)&Bs[0][r0t * 40 + j0 * 8] =
            *(const uint4*)&Bsrc[(size_t)(n0 + r0t) * 256 + bb + j0 * 8];
        *(uint4*)&Bs[0][r1t * 40 + j1 * 8] =
            *(const uint4*)&Bsrc[(size_t)(n0 + r1t) * 256 + bb + j1 * 8];
    }
    __syncthreads();

    uint4 rA0, rA1, rB0, rB1;
    for (int c = 0; c < 24; c++) {
        int s = c & 1;
        bool pf = (c + 1 < 24);
        if (pf) {
            int ab, bb; const __nv_bfloat16* Bsrc;
            chunk_src(c + 1, ab, Bsrc, bb);
            rA0 = *(const uint4*)&g_Abig[(size_t)(row0 + r0t) * 512 + ab + j0 * 8];
            rA1 = *(const uint4*)&g_Abig[(size_t)(row0 + r1t) * 512 + ab + j1 * 8];
            rB0 = *(const uint4*)&Bsrc[(size_t)(n0 + r0t) * 256 + bb + j0 * 8];
            rB1 = *(const uint4*)&Bsrc[(size_t)(n0 + r1t) * 256 + bb + j1 * 8];
        }
#pragma unroll
        for (int ks = 0; ks < 2; ks++) {
            int kb = ks * 16;
            uint32_t a[2][4], b[4][4];
#pragma unroll
            for (int mt = 0; mt < 2; mt++) {
                int rr = warp_m * 32 + mt * 16 + (lane & 15);
                int cc = kb + ((lane >> 4) << 3);
                uint32_t addr = (uint32_t)__cvta_generic_to_shared(&As[s][rr * 40 + cc]);
                ldsm_x4(a[mt][0], a[mt][1], a[mt][2], a[mt][3], addr);
            }
#pragma unroll
            for (int nt2 = 0; nt2 < 4; nt2++) {
                int rr = warp_n * 64 + nt2 * 16 + (lane & 7) + ((lane >> 4) << 3);
                int cc = kb + (((lane >> 3) & 1) << 3);
                uint32_t addr = (uint32_t)__cvta_generic_to_shared(&Bs[s][rr * 40 + cc]);
                ldsm_x4(b[nt2][0], b[nt2][1], b[nt2][2], b[nt2][3], addr);
            }
#pragma unroll
            for (int mt = 0; mt < 2; mt++)
#pragma unroll
                for (int nt = 0; nt < 8; nt++)
                    mma_16816(acc[mt][nt], a[mt][0], a[mt][1], a[mt][2], a[mt][3],
                              b[nt >> 1][(nt & 1) * 2], b[nt >> 1][(nt & 1) * 2 + 1]);
        }
        __syncthreads();
        if (pf) {
            *(uint4*)&As[s ^ 1][r0t * 40 + j0 * 8] = rA0;
            *(uint4*)&As[s ^ 1][r1t * 40 + j1 * 8] = rA1;
            *(uint4*)&Bs[s ^ 1][r0t * 40 + j0 * 8] = rB0;
            *(uint4*)&Bs[s ^ 1][r1t * 40 + j1 * 8] = rB1;
            __syncthreads();
        }
    }

    // epilogue: bias + relu -> g_h1
    float2 bias[8];
#pragma unroll
    for (int nt = 0; nt < 8; nt++) {
        int colg = n0 + warp_n * 64 + nt * 8 + (lane & 3) * 2;
        bias[nt] = *(const float2*)&b1[colg];
    }
#pragma unroll
    for (int mt = 0; mt < 2; mt++) {
        int rbase = row0 + warp_m * 32 + mt * 16 + (lane >> 2);
#pragma unroll
        for (int half = 0; half < 2; half++) {
            int rg = rbase + half * 8;
            if (rg < N_DST0) {
                float* dst = g_h1 + (size_t)rg * HF + n0 + warp_n * 64 + (lane & 3) * 2;
#pragma unroll
                for (int nt = 0; nt < 8; nt++) {
                    float2 v;
                    v.x = fmaxf(acc[mt][nt][half * 2 + 0] + bias[nt].x, 0.f);
                    v.y = fmaxf(acc[mt][nt][half * 2 + 1] + bias[nt].y, 0.f);
                    *(float2*)(dst + nt * 8) = v;
                }
            }
        }
    }
}

// ---------------- 6) projections: p1 = h1@Wn2 ; self2 = h1[:100k]@Ws2 -----------
__global__ __launch_bounds__(256) void proj_kernel(const float* __restrict__ Wn2,
                                                   const float* __restrict__ Ws2) {
    __shared__ __align__(16) float h1s[16 * 260];
    __shared__ __align__(16) float wT[16 * 260];
    int tid = threadIdx.x;
    for (int i = tid; i < 4096; i += 256) {
        int k = i >> 4, cc = i & 15;
        wT[cc * 260 + k] = (cc < 8) ? Wn2[k * 8 + cc] : Ws2[k * 8 + (cc - 8)];
    }
    int r0 = blockIdx.x * 16;
    for (int j = tid; j < 1024; j += 256) {
        int i = j >> 6, k4 = j & 63;
        *(float4*)&h1s[i * 260 + k4 * 4] =
            *(const float4*)&g_h1[(size_t)(r0 + i) * HF + k4 * 4];
    }
    __syncthreads();

    int row = tid >> 4, cc = tid & 15;
    const float* hp = &h1s[row * 260];
    const float* wp = &wT[cc * 260];
    float acc = 0.f;
#pragma unroll 16
    for (int k = 0; k < 256; k += 4) {
        float4 h4 = *(const float4*)(hp + k);
        float4 w4 = *(const float4*)(wp + k);
        acc += h4.x * w4.x + h4.y * w4.y + h4.z * w4.z + h4.w * w4.w;
    }
    int m = r0 + row;
    if (cc < 8)          g_p1[m * NC + cc] = acc;
    else if (m < N_DST1) g_self2[m * NC + (cc - 8)] = acc;
}

// ---------------- 7) layer-2 edge aggregation -----------------------------------
__global__ __launch_bounds__(256) void edge2_kernel(const int* __restrict__ src,
                                                    const int* __restrict__ dst) {
    int e = blockIdx.x * blockDim.x + threadIdx.x;
    if (e >= E1) return;
    int s = src[e], d = dst[e];
    float4 v0 = *(const float4*)(g_p1 + (size_t)s * NC);
    float4 v1 = *(const float4*)(g_p1 + (size_t)s * NC + 4);
    red_add_v4(g_agg2 + (size_t)d * NC, v0);
    red_add_v4(g_agg2 + (size_t)d * NC + 4, v1);
    atomicAdd(&g_deg2[d], 1.0f);
}

// ---------------- 8) final ------------------------------------------------------
__global__ __launch_bounds__(256) void final_kernel(const float* __restrict__ b2,
                                                    float* __restrict__ out) {
    int t = blockIdx.x * blockDim.x + threadIdx.x;
    if (t >= N_DST1 * 2) return;
    int m = t >> 1, q = t & 1;
    float inv = 1.f / fmaxf(g_deg2[m], 1.f);
    float4 a = *(float4*)&g_agg2[m * NC + q * 4];
    float4 s = *(float4*)&g_self2[m * NC + q * 4];
    float4 bb = *(const float4*)(b2 + q * 4);
    float4 o;
    o.x = s.x + a.x * inv + bb.x;
    o.y = s.y + a.y * inv + bb.y;
    o.z = s.z + a.z * inv + bb.z;
    o.w = s.w + a.w * inv + bb.w;
    *(float4*)&out[m * NC + q * 4] = o;
}

// ---------------- host ----------------------------------------------------------
extern "C" void kernel_launch(void* const* d_in, const int* in_sizes, int n_in,
                              void* d_out, int out_size) {
    const float* x    = (const float*)d_in[0];
    const int*   src0 = (const int*)d_in[1];
    const int*   dst0 = (const int*)d_in[2];
    const int*   src1 = (const int*)d_in[3];
    const int*   dst1 = (const int*)d_in[4];

    int ie = 5;
    while (ie < n_in && in_sizes[ie] != 24 * INF) ie++;
    const float* emb = (const float*)d_in[ie];
    const float* Ws1 = (const float*)d_in[ie + 1];
    const float* Wn1 = (const float*)d_in[ie + 2];
    const float* b1  = (const float*)d_in[ie + 3];
    const float* Ws2 = (const float*)d_in[ie + 4];
    const float* Wn2 = (const float*)d_in[ie + 5];
    const float* b2  = (const float*)d_in[ie + 6];

    zero_kernel<<<26076, 256>>>();
    gate_kernel<<<(N_SRC0 * 32) / 256, 256>>>(x, emb);
    edge1_kernel<<<(E0 * 32 + 255) / 256, 256>>>(src0, dst0);
    convertB_kernel<<<256, 256>>>(Ws1, Wn1);
    convertA_kernel<<<M_ROWS_PAD, 256>>>();
    dim3 g1(M_ROWS_PAD / 128, 2);
    gemm1_mma_kernel<<<g1, 256>>>(b1);
    proj_kernel<<<N_DST0 / 16, 256>>>(Wn2, Ws2);
    edge2_kernel<<<(E1 + 255) / 256, 256>>>(src1, dst1);
    final_kernel<<<(N_DST1 * 2 + 255) / 256, 256>>>(b2, (float*)d_out);
}